// round 12
// baseline (speedup 1.0000x reference)
#include <cuda_runtime.h>
#include <math.h>

#define BATCH 4
#define NC 16
#define NF 64
#define VV 262144
#define TOPK 100
#define TILE 64
#define CAND_MAX 4096
#define CANDS 2048
#define NBINS 65536
#define THETA 0.9f
#define INV_TAU 10.0f

#define GA 592    // kA blocks = 4 blocks/SM * 148 SMs (one full wave)
#define GB 1024   // kB blocks (1024*256*4 = BATCH*VV elements)

// ---------------- scratch (device globals; no allocations allowed) ----------------
__device__ float    g_weights[BATCH * VV];        // 4 MB
__device__ unsigned g_hist[BATCH * NBINS];        // 1 MB
__device__ float    g_sums[NC * NF];
__device__ int      g_cnt[NC];
__device__ int      g_thresh[BATCH];
__device__ unsigned g_ccnt[BATCH];
__device__ float    g_cand_val[BATCH * CAND_MAX];
__device__ int      g_cand_idx[BATCH * CAND_MAX];

// ---------------- init: zero all accumulators + output ----------------------------
__global__ void kInit(float* out) {
    int gid = blockIdx.x * blockDim.x + threadIdx.x;   // 65536 threads
    ((uint4*)g_hist)[gid] = make_uint4(0u, 0u, 0u, 0u);
    if (gid < NC * NF) g_sums[gid] = 0.f;
    if (gid < NC)      g_cnt[gid] = 0;
    if (gid < BATCH)   g_ccnt[gid] = 0u;
    if (gid == 0)      out[0] = 0.f;
}

// ---------------- kB: weights = prod_c proba + 16-bit key histogram ---------------
__global__ void kB(const float* __restrict__ proba) {
    int gid = blockIdx.x * 256 + threadIdx.x;   // 0..262143
    int b = gid >> 16;
    int r = gid & 65535;
    int v0 = r << 2;
    const float4* p4 = (const float4*)(proba + ((size_t)b * NC << 18) + v0);
    float4 acc = make_float4(1.f, 1.f, 1.f, 1.f);
    #pragma unroll
    for (int c = 0; c < NC; c++) {
        float4 p = p4[(size_t)c * (VV / 4)];
        acc.x *= p.x; acc.y *= p.y; acc.z *= p.z; acc.w *= p.w;
    }
    *(float4*)(g_weights + ((size_t)b << 18) + v0) = acc;
    unsigned base = (unsigned)b << 16;
    atomicAdd(&g_hist[base | (__float_as_uint(acc.x) >> 16)], 1u);
    atomicAdd(&g_hist[base | (__float_as_uint(acc.y) >> 16)], 1u);
    atomicAdd(&g_hist[base | (__float_as_uint(acc.z) >> 16)], 1u);
    atomicAdd(&g_hist[base | (__float_as_uint(acc.w) >> 16)], 1u);
}

// ---------------- kA: per-class feature sums (register-pipelined) -----------------
__global__ void __launch_bounds__(256, 4)
kA(const float* __restrict__ y, const float* __restrict__ emb) {
    __shared__ float s_emb[TILE][NF + 1];   // [v][f], stride 65
    __shared__ float s_wacc[8][NC][32];     // warp-private accumulators
    __shared__ int   s_lab[TILE];
    __shared__ int   s_cnt[NC];

    int tid = threadIdx.x;
    int bid = blockIdx.x;
    int w    = tid >> 5;
    int lane = tid & 31;

    for (int i = tid; i < 8 * NC * 32; i += 256) ((float*)s_wacc)[i] = 0.f;
    if (tid < NC) s_cnt[tid] = 0;
    __syncthreads();

    const int tilesPerB = VV / TILE;            // 4096
    const int nTiles    = BATCH * tilesPerB;    // 16384

    int yc  = tid >> 4;        // class 0..15
    int yv4 = tid & 15;        // v4-group 0..15
    // conflict-free staging: ef in {tid>>3, tid>>3+32}, v4-groups {tid&7, (tid&7)+8}
    int ef  = tid >> 3;        // 0..31
    int ev4 = tid & 7;         // 0..7

    float4 e0, e1, e2, e3, yy;
    {
        int t = bid;
        int b  = t / tilesPerB;
        int v0 = (t - b * tilesPerB) * TILE;
        const float4* ep4 = (const float4*)(emb + (size_t)b * NF * VV + v0);
        e0 = ep4[(size_t)(ef +  0) * (VV / 4) + ev4];
        e1 = ep4[(size_t)(ef +  0) * (VV / 4) + ev4 + 8];
        e2 = ep4[(size_t)(ef + 32) * (VV / 4) + ev4];
        e3 = ep4[(size_t)(ef + 32) * (VV / 4) + ev4 + 8];
        yy = *(const float4*)(y + ((size_t)b * NC + yc) * VV + v0 + (yv4 << 2));
    }
    float4 ne0 = e0, ne1 = e1, ne2 = e2, ne3 = e3, nyy = yy;

    for (int t = bid; t < nTiles; t += GA) {
        // commit current tile's registers to shared
        {
            int hits = 0;
            if (yy.x > 0.5f) { s_lab[(yv4 << 2) + 0] = yc; hits++; }
            if (yy.y > 0.5f) { s_lab[(yv4 << 2) + 1] = yc; hits++; }
            if (yy.z > 0.5f) { s_lab[(yv4 << 2) + 2] = yc; hits++; }
            if (yy.w > 0.5f) { s_lab[(yv4 << 2) + 3] = yc; hits++; }
            if (hits) atomicAdd(&s_cnt[yc], hits);

            int j0 = ev4 << 2;
            int j1 = (ev4 + 8) << 2;
            s_emb[j0 + 0][ef +  0] = e0.x; s_emb[j0 + 1][ef +  0] = e0.y;
            s_emb[j0 + 2][ef +  0] = e0.z; s_emb[j0 + 3][ef +  0] = e0.w;
            s_emb[j1 + 0][ef +  0] = e1.x; s_emb[j1 + 1][ef +  0] = e1.y;
            s_emb[j1 + 2][ef +  0] = e1.z; s_emb[j1 + 3][ef +  0] = e1.w;
            s_emb[j0 + 0][ef + 32] = e2.x; s_emb[j0 + 1][ef + 32] = e2.y;
            s_emb[j0 + 2][ef + 32] = e2.z; s_emb[j0 + 3][ef + 32] = e2.w;
            s_emb[j1 + 0][ef + 32] = e3.x; s_emb[j1 + 1][ef + 32] = e3.y;
            s_emb[j1 + 2][ef + 32] = e3.z; s_emb[j1 + 3][ef + 32] = e3.w;
        }
        __syncthreads();

        // prefetch next tile (overlaps with accumulate below)
        int tn = t + GA;
        if (tn < nTiles) {
            int b  = tn / tilesPerB;
            int v0 = (tn - b * tilesPerB) * TILE;
            const float4* ep4 = (const float4*)(emb + (size_t)b * NF * VV + v0);
            ne0 = ep4[(size_t)(ef +  0) * (VV / 4) + ev4];
            ne1 = ep4[(size_t)(ef +  0) * (VV / 4) + ev4 + 8];
            ne2 = ep4[(size_t)(ef + 32) * (VV / 4) + ev4];
            ne3 = ep4[(size_t)(ef + 32) * (VV / 4) + ev4 + 8];
            nyy = *(const float4*)(y + ((size_t)b * NC + yc) * VV + v0 + (yv4 << 2));
        }

        // accumulate: warp w -> f-half (w&1), voxels v = (w>>1) + 4k
        int f = ((w & 1) << 5) + lane;
        #pragma unroll
        for (int v = (w >> 1); v < TILE; v += 4) {
            int lab = s_lab[v];
            s_wacc[w][lab][lane] += s_emb[v][f];
        }
        __syncthreads();

        e0 = ne0; e1 = ne1; e2 = ne2; e3 = ne3; yy = nyy;
    }

    // flush block-private accumulators
    for (int s = tid; s < NC * NF; s += 256) {
        int c = s >> 6, f = s & 63;
        int half = f >> 5, fl = f & 31;
        float sum = 0.f;
        #pragma unroll
        for (int ww = 0; ww < 4; ww++) sum += s_wacc[half + 2 * ww][c][fl];
        atomicAdd(&g_sums[s], sum);
    }
    if (tid < NC) atomicAdd(&g_cnt[tid], s_cnt[tid]);
}

// ---------------- kThresh: radix-select threshold key, 1024 threads/batch --------
__global__ void __launch_bounds__(1024) kThresh() {
    int b = blockIdx.x, t = threadIdx.x;    // 1024 threads
    const uint4* h4 = (const uint4*)(g_hist + b * NBINS);

    unsigned s = 0;
    #pragma unroll
    for (int i = 0; i < 16; i++) {
        uint4 v = h4[t * 16 + i];   // bins [64t, 64t+64)
        s += v.x + v.y + v.z + v.w;
    }

    __shared__ unsigned suf[1025];
    suf[t] = s;
    if (t == 0) suf[1024] = 0;
    __syncthreads();

    #pragma unroll
    for (int off = 1; off < 1024; off <<= 1) {
        unsigned add = (t + off < 1024) ? suf[t + off] : 0u;
        __syncthreads();
        suf[t] += add;
        __syncthreads();
    }

    if (suf[t] >= TOPK && suf[t + 1] < TOPK) {
        unsigned run = suf[t + 1];
        const unsigned* h = g_hist + b * NBINS + t * 64;
        int T = t * 64;
        for (int i = 63; i >= 0; i--) {
            run += h[i];
            if (run >= TOPK) { T = t * 64 + i; break; }
        }
        g_thresh[b] = T;
    }
}

// ---------------- kCollect: candidates >= threshold (vectorized) -----------------
__global__ void kCollect() {
    int gid = blockIdx.x * 256 + threadIdx.x;   // 262144
    int b = gid >> 16;
    int r = gid & 65535;
    int v0 = r << 2;
    float4 w4 = *(const float4*)(g_weights + ((size_t)b << 18) + v0);
    int th = g_thresh[b];
    float wv[4] = {w4.x, w4.y, w4.z, w4.w};
    #pragma unroll
    for (int k = 0; k < 4; k++) {
        if ((int)(__float_as_uint(wv[k]) >> 16) >= th) {
            unsigned pos = atomicAdd(&g_ccnt[b], 1u);
            if (pos < CAND_MAX) {
                g_cand_val[b * CAND_MAX + pos] = wv[k];
                g_cand_idx[b * CAND_MAX + pos] = v0 + k;
            }
        }
    }
}

// ---------------- kLossSel: top-100 rank + contrastive loss, block per (b,class) --
#define FCH 32
__global__ void kLossSel(const float* __restrict__ emb, const float* __restrict__ y,
                         float* out) {
    int b  = blockIdx.x >> 4;
    int cc = blockIdx.x & 15;
    int tid = threadIdx.x;   // 256

    __shared__ float s_val[CANDS];       // 8 KB
    __shared__ int   s_idx[CANDS];       // 8 KB
    __shared__ int   s_top[TOPK];
    __shared__ int   s_labk[TOPK];
    __shared__ float s_l[TOPK * FCH];    // 12.8 KB
    __shared__ float s_N[TOPK * FCH];    // 12.8 KB
    __shared__ float s_avg[NC * NF];     // 4 KB
    __shared__ int   s_mem[TOPK];
    __shared__ int   s_m;
    __shared__ float s_red[256];

    int n = min((int)g_ccnt[b], CANDS);
    for (int i = tid; i < n; i += 256) {
        s_val[i] = g_cand_val[b * CAND_MAX + i];
        s_idx[i] = g_cand_idx[b * CAND_MAX + i];
    }
    for (int i = tid; i < NC * NF; i += 256) {
        int c = i >> 6;
        int cnt = g_cnt[c];
        float mean = g_sums[i] / (float)max(cnt, 1);
        s_avg[i] = (cnt > 0) ? THETA * mean : 0.f;
    }
    __syncthreads();

    // exact top-100 by rank (jax tie-break: value desc, index asc)
    for (int i = tid; i < n; i += 256) {
        float vi = s_val[i]; int ii = s_idx[i];
        int rank = 0;
        for (int j = 0; j < n; j++) {
            float vj = s_val[j];
            rank += (vj > vi) || (vj == vi && s_idx[j] < ii);
        }
        if (rank < TOPK) s_top[rank] = ii;
    }
    __syncthreads();

    // labels of selected voxels (one-hot scan of y)
    for (int k = tid; k < TOPK; k += 256) {
        int idx = s_top[k];
        int lab = 0;
        #pragma unroll
        for (int c = 0; c < NC; c++)
            if (y[((size_t)b * NC + c) * VV + idx] > 0.5f) lab = c;
        s_labk[k] = lab;
    }
    __syncthreads();

    // deterministic member compaction for class cc
    for (int k = tid; k < TOPK; k += 256) {
        if (s_labk[k] == cc) {
            int pos = 0;
            for (int kk = 0; kk < k; kk++) pos += (s_labk[kk] == cc);
            s_mem[pos] = s_top[k];   // voxel index
        }
    }
    if (tid == 0) {
        int mm = 0;
        for (int kk = 0; kk < TOPK; kk++) mm += (s_labk[kk] == cc);
        s_m = mm;
    }
    __syncthreads();
    int m = s_m;
    if (m == 0) return;   // uniform exit

    float local = 0.f;
    int npairs = m * m;

    #pragma unroll
    for (int fc = 0; fc < NF / FCH; fc++) {
        int f0 = fc * FCH;

        for (int q = tid; q < m * FCH; q += 256) {
            int j = q >> 5, ff = (q & (FCH - 1)) + f0;
            float he = emb[((size_t)b * NF + ff) * VV + s_mem[j]];
            float S = 0.f, lc = 0.f, ec = 1.f;
            #pragma unroll
            for (int c2 = 0; c2 < NC; c2++) {
                float l = he * s_avg[c2 * NF + ff] * INV_TAU;
                float e = expf(l);
                S += e;
                if (c2 == cc) { lc = l; ec = e; }
            }
            s_l[q] = lc;
            s_N[q] = S - ec;
        }
        __syncthreads();

        for (int pp = tid; pp < npairs; pp += 256) {
            int i = pp / m;
            int j = pp - i * m;
            const float* li = s_l + i * FCH;
            const float* Nj = s_N + j * FCH;
            #pragma unroll 8
            for (int ff = 0; ff < FCH; ff++) {
                float l = li[ff];
                local += logf(expf(l) + Nj[ff]) - l;
            }
        }
        __syncthreads();
    }

    s_red[tid] = local;
    __syncthreads();
    for (int s = 128; s > 0; s >>= 1) {
        if (tid < s) s_red[tid] += s_red[tid + s];
        __syncthreads();
    }
    if (tid == 0) {
        float denom = (float)m * (float)m * (float)NF;
        atomicAdd(out, -(s_red[0] / denom) / (float)BATCH);
    }
}

// ---------------- stream/event side resources (host objects, created pre-main) ----
struct ForkRes {
    cudaStream_t s2;
    cudaEvent_t  evB, evC;
    ForkRes() {
        cudaStreamCreateWithFlags(&s2, cudaStreamNonBlocking);
        cudaEventCreateWithFlags(&evB, cudaEventDisableTiming);
        cudaEventCreateWithFlags(&evC, cudaEventDisableTiming);
    }
};
static ForkRes g_fork;

// ---------------- launch ----------------------------------------------------------
extern "C" void kernel_launch(void* const* d_in, const int* in_sizes, int n_in,
                              void* d_out, int out_size) {
    const float* proba = (const float*)d_in[0];
    const float* y     = (const float*)d_in[1];
    const float* emb   = (const float*)d_in[2];
    float* out = (float*)d_out;
    (void)in_sizes; (void)n_in; (void)out_size;

    kInit<<<256, 256>>>(out);
    kB<<<GB, 256>>>(proba);

    // fork: thresh/collect depend only on kB; run them beside kA
    cudaEventRecord(g_fork.evB, 0);
    cudaStreamWaitEvent(g_fork.s2, g_fork.evB, 0);
    kThresh<<<BATCH, 1024, 0, g_fork.s2>>>();
    kCollect<<<1024, 256, 0, g_fork.s2>>>();
    cudaEventRecord(g_fork.evC, g_fork.s2);

    kA<<<GA, 256>>>(y, emb);

    // join: loss needs kA sums + collected candidates
    cudaStreamWaitEvent(0, g_fork.evC, 0);
    kLossSel<<<BATCH * NC, 256>>>(emb, y, out);
}

// round 13
// speedup vs baseline: 1.0402x; 1.0402x over previous
#include <cuda_runtime.h>
#include <math.h>

#define BATCH 4
#define NC 16
#define NF 64
#define VV 262144
#define TOPK 100
#define TILE 64
#define CAND_MAX 4096
#define CANDS 2048
#define NBINS 65536
#define THETA 0.9f
#define INV_TAU 10.0f

#define GA 592    // kA blocks = 4 blocks/SM * 148 SMs (one full wave)
#define GB 1024   // kB blocks (1024*256*4 = BATCH*VV elements)

// ---------------- scratch (device globals; no allocations allowed) ----------------
__device__ float    g_weights[BATCH * VV];        // 4 MB
__device__ unsigned g_hist[BATCH * NBINS];        // 1 MB
__device__ float    g_sums[NC * NF];
__device__ int      g_cnt[NC];
__device__ int      g_thresh[BATCH];
__device__ unsigned g_ccnt[BATCH];
__device__ float    g_cand_val[BATCH * CAND_MAX];
__device__ int      g_cand_idx[BATCH * CAND_MAX];

// ---------------- init: zero all accumulators + output ----------------------------
__global__ void kInit(float* out) {
    int gid = blockIdx.x * blockDim.x + threadIdx.x;   // 65536 threads
    ((uint4*)g_hist)[gid] = make_uint4(0u, 0u, 0u, 0u);
    if (gid < NC * NF) g_sums[gid] = 0.f;
    if (gid < NC)      g_cnt[gid] = 0;
    if (gid < BATCH)   g_ccnt[gid] = 0u;
    if (gid == 0)      out[0] = 0.f;
}

// ---------------- kB: weights = prod_c proba + 16-bit key histogram ---------------
__global__ void kB(const float* __restrict__ proba) {
    int gid = blockIdx.x * 256 + threadIdx.x;   // 0..262143
    int b = gid >> 16;
    int r = gid & 65535;
    int v0 = r << 2;
    const float4* p4 = (const float4*)(proba + ((size_t)b * NC << 18) + v0);
    float4 acc = make_float4(1.f, 1.f, 1.f, 1.f);
    #pragma unroll
    for (int c = 0; c < NC; c++) {
        float4 p = p4[(size_t)c * (VV / 4)];
        acc.x *= p.x; acc.y *= p.y; acc.z *= p.z; acc.w *= p.w;
    }
    *(float4*)(g_weights + ((size_t)b << 18) + v0) = acc;
    unsigned base = (unsigned)b << 16;
    atomicAdd(&g_hist[base | (__float_as_uint(acc.x) >> 16)], 1u);
    atomicAdd(&g_hist[base | (__float_as_uint(acc.y) >> 16)], 1u);
    atomicAdd(&g_hist[base | (__float_as_uint(acc.z) >> 16)], 1u);
    atomicAdd(&g_hist[base | (__float_as_uint(acc.w) >> 16)], 1u);
}

// ---------------- kA: per-class feature sums (register-pipelined) -----------------
__global__ void __launch_bounds__(256, 4)
kA(const float* __restrict__ y, const float* __restrict__ emb) {
    __shared__ float s_emb[TILE][NF + 1];   // [v][f], stride 65
    __shared__ float s_wacc[8][NC][32];     // warp-private accumulators
    __shared__ int   s_lab[TILE];
    __shared__ int   s_cnt[NC];

    int tid = threadIdx.x;
    int bid = blockIdx.x;
    int w    = tid >> 5;
    int lane = tid & 31;

    for (int i = tid; i < 8 * NC * 32; i += 256) ((float*)s_wacc)[i] = 0.f;
    if (tid < NC) s_cnt[tid] = 0;
    __syncthreads();

    const int tilesPerB = VV / TILE;            // 4096
    const int nTiles    = BATCH * tilesPerB;    // 16384

    int yc  = tid >> 4;        // class 0..15
    int yv4 = tid & 15;        // v4-group 0..15
    // conflict-free staging: ef in {tid>>3, tid>>3+32}, v4-groups {tid&7, (tid&7)+8}
    int ef  = tid >> 3;        // 0..31
    int ev4 = tid & 7;         // 0..7

    float4 e0, e1, e2, e3, yy;
    {
        int t = bid;
        int b  = t / tilesPerB;
        int v0 = (t - b * tilesPerB) * TILE;
        const float4* ep4 = (const float4*)(emb + (size_t)b * NF * VV + v0);
        e0 = ep4[(size_t)(ef +  0) * (VV / 4) + ev4];
        e1 = ep4[(size_t)(ef +  0) * (VV / 4) + ev4 + 8];
        e2 = ep4[(size_t)(ef + 32) * (VV / 4) + ev4];
        e3 = ep4[(size_t)(ef + 32) * (VV / 4) + ev4 + 8];
        yy = *(const float4*)(y + ((size_t)b * NC + yc) * VV + v0 + (yv4 << 2));
    }
    float4 ne0 = e0, ne1 = e1, ne2 = e2, ne3 = e3, nyy = yy;

    for (int t = bid; t < nTiles; t += GA) {
        // commit current tile's registers to shared
        {
            int hits = 0;
            if (yy.x > 0.5f) { s_lab[(yv4 << 2) + 0] = yc; hits++; }
            if (yy.y > 0.5f) { s_lab[(yv4 << 2) + 1] = yc; hits++; }
            if (yy.z > 0.5f) { s_lab[(yv4 << 2) + 2] = yc; hits++; }
            if (yy.w > 0.5f) { s_lab[(yv4 << 2) + 3] = yc; hits++; }
            if (hits) atomicAdd(&s_cnt[yc], hits);

            int j0 = ev4 << 2;
            int j1 = (ev4 + 8) << 2;
            s_emb[j0 + 0][ef +  0] = e0.x; s_emb[j0 + 1][ef +  0] = e0.y;
            s_emb[j0 + 2][ef +  0] = e0.z; s_emb[j0 + 3][ef +  0] = e0.w;
            s_emb[j1 + 0][ef +  0] = e1.x; s_emb[j1 + 1][ef +  0] = e1.y;
            s_emb[j1 + 2][ef +  0] = e1.z; s_emb[j1 + 3][ef +  0] = e1.w;
            s_emb[j0 + 0][ef + 32] = e2.x; s_emb[j0 + 1][ef + 32] = e2.y;
            s_emb[j0 + 2][ef + 32] = e2.z; s_emb[j0 + 3][ef + 32] = e2.w;
            s_emb[j1 + 0][ef + 32] = e3.x; s_emb[j1 + 1][ef + 32] = e3.y;
            s_emb[j1 + 2][ef + 32] = e3.z; s_emb[j1 + 3][ef + 32] = e3.w;
        }
        __syncthreads();

        // prefetch next tile (overlaps with accumulate below)
        int tn = t + GA;
        if (tn < nTiles) {
            int b  = tn / tilesPerB;
            int v0 = (tn - b * tilesPerB) * TILE;
            const float4* ep4 = (const float4*)(emb + (size_t)b * NF * VV + v0);
            ne0 = ep4[(size_t)(ef +  0) * (VV / 4) + ev4];
            ne1 = ep4[(size_t)(ef +  0) * (VV / 4) + ev4 + 8];
            ne2 = ep4[(size_t)(ef + 32) * (VV / 4) + ev4];
            ne3 = ep4[(size_t)(ef + 32) * (VV / 4) + ev4 + 8];
            nyy = *(const float4*)(y + ((size_t)b * NC + yc) * VV + v0 + (yv4 << 2));
        }

        // accumulate: warp w -> f-half (w&1), voxels v = (w>>1) + 4k
        int f = ((w & 1) << 5) + lane;
        #pragma unroll
        for (int v = (w >> 1); v < TILE; v += 4) {
            int lab = s_lab[v];
            s_wacc[w][lab][lane] += s_emb[v][f];
        }
        __syncthreads();

        e0 = ne0; e1 = ne1; e2 = ne2; e3 = ne3; yy = nyy;
    }

    // flush block-private accumulators
    for (int s = tid; s < NC * NF; s += 256) {
        int c = s >> 6, f = s & 63;
        int half = f >> 5, fl = f & 31;
        float sum = 0.f;
        #pragma unroll
        for (int ww = 0; ww < 4; ww++) sum += s_wacc[half + 2 * ww][c][fl];
        atomicAdd(&g_sums[s], sum);
    }
    if (tid < NC) atomicAdd(&g_cnt[tid], s_cnt[tid]);
}

// ---------------- kThresh: radix-select threshold key, 1024 threads/batch --------
__global__ void __launch_bounds__(1024) kThresh() {
    int b = blockIdx.x, t = threadIdx.x;    // 1024 threads
    const uint4* h4 = (const uint4*)(g_hist + b * NBINS);

    unsigned s = 0;
    #pragma unroll
    for (int i = 0; i < 16; i++) {
        uint4 v = h4[t * 16 + i];   // bins [64t, 64t+64)
        s += v.x + v.y + v.z + v.w;
    }

    __shared__ unsigned suf[1025];
    suf[t] = s;
    if (t == 0) suf[1024] = 0;
    __syncthreads();

    #pragma unroll
    for (int off = 1; off < 1024; off <<= 1) {
        unsigned add = (t + off < 1024) ? suf[t + off] : 0u;
        __syncthreads();
        suf[t] += add;
        __syncthreads();
    }

    if (suf[t] >= TOPK && suf[t + 1] < TOPK) {
        unsigned run = suf[t + 1];
        const unsigned* h = g_hist + b * NBINS + t * 64;
        int T = t * 64;
        for (int i = 63; i >= 0; i--) {
            run += h[i];
            if (run >= TOPK) { T = t * 64 + i; break; }
        }
        g_thresh[b] = T;
    }
}

// ---------------- kCollect: candidates >= threshold (vectorized) -----------------
__global__ void kCollect() {
    int gid = blockIdx.x * 256 + threadIdx.x;   // 262144
    int b = gid >> 16;
    int r = gid & 65535;
    int v0 = r << 2;
    float4 w4 = *(const float4*)(g_weights + ((size_t)b << 18) + v0);
    int th = g_thresh[b];
    float wv[4] = {w4.x, w4.y, w4.z, w4.w};
    #pragma unroll
    for (int k = 0; k < 4; k++) {
        if ((int)(__float_as_uint(wv[k]) >> 16) >= th) {
            unsigned pos = atomicAdd(&g_ccnt[b], 1u);
            if (pos < CAND_MAX) {
                g_cand_val[b * CAND_MAX + pos] = wv[k];
                g_cand_idx[b * CAND_MAX + pos] = v0 + k;
            }
        }
    }
}

// ---------------- kLossSel: top-100 rank + contrastive loss, block per (b,class) --
#define FCH 32
__global__ void kLossSel(const float* __restrict__ emb, const float* __restrict__ y,
                         float* out) {
    int b  = blockIdx.x >> 4;
    int cc = blockIdx.x & 15;
    int tid = threadIdx.x;   // 256

    __shared__ float s_val[CANDS];       // 8 KB
    __shared__ int   s_idx[CANDS];       // 8 KB
    __shared__ int   s_top[TOPK];
    __shared__ int   s_labk[TOPK];
    __shared__ float s_l[TOPK * FCH];    // 12.8 KB
    __shared__ float s_N[TOPK * FCH];    // 12.8 KB
    __shared__ float s_avg[NC * NF];     // 4 KB
    __shared__ int   s_mem[TOPK];
    __shared__ int   s_m;
    __shared__ float s_red[256];

    int n = min((int)g_ccnt[b], CANDS);
    for (int i = tid; i < n; i += 256) {
        s_val[i] = g_cand_val[b * CAND_MAX + i];
        s_idx[i] = g_cand_idx[b * CAND_MAX + i];
    }
    for (int i = tid; i < NC * NF; i += 256) {
        int c = i >> 6;
        int cnt = g_cnt[c];
        float mean = g_sums[i] / (float)max(cnt, 1);
        s_avg[i] = (cnt > 0) ? THETA * mean : 0.f;
    }
    __syncthreads();

    // exact top-100 by rank (jax tie-break: value desc, index asc)
    for (int i = tid; i < n; i += 256) {
        float vi = s_val[i]; int ii = s_idx[i];
        int rank = 0;
        for (int j = 0; j < n; j++) {
            float vj = s_val[j];
            rank += (vj > vi) || (vj == vi && s_idx[j] < ii);
        }
        if (rank < TOPK) s_top[rank] = ii;
    }
    __syncthreads();

    // labels of selected voxels (one-hot scan of y)
    for (int k = tid; k < TOPK; k += 256) {
        int idx = s_top[k];
        int lab = 0;
        #pragma unroll
        for (int c = 0; c < NC; c++)
            if (y[((size_t)b * NC + c) * VV + idx] > 0.5f) lab = c;
        s_labk[k] = lab;
    }
    __syncthreads();

    // deterministic member compaction for class cc
    for (int k = tid; k < TOPK; k += 256) {
        if (s_labk[k] == cc) {
            int pos = 0;
            for (int kk = 0; kk < k; kk++) pos += (s_labk[kk] == cc);
            s_mem[pos] = s_top[k];   // voxel index
        }
    }
    if (tid == 0) {
        int mm = 0;
        for (int kk = 0; kk < TOPK; kk++) mm += (s_labk[kk] == cc);
        s_m = mm;
    }
    __syncthreads();
    int m = s_m;
    if (m == 0) return;   // uniform exit

    float local = 0.f;
    int npairs = m * m;

    #pragma unroll
    for (int fc = 0; fc < NF / FCH; fc++) {
        int f0 = fc * FCH;

        for (int q = tid; q < m * FCH; q += 256) {
            int j = q >> 5, ff = (q & (FCH - 1)) + f0;
            float he = emb[((size_t)b * NF + ff) * VV + s_mem[j]];
            float S = 0.f, lc = 0.f, ec = 1.f;
            #pragma unroll
            for (int c2 = 0; c2 < NC; c2++) {
                float l = he * s_avg[c2 * NF + ff] * INV_TAU;
                float e = expf(l);
                S += e;
                if (c2 == cc) { lc = l; ec = e; }
            }
            s_l[q] = lc;
            s_N[q] = S - ec;
        }
        __syncthreads();

        for (int pp = tid; pp < npairs; pp += 256) {
            int i = pp / m;
            int j = pp - i * m;
            const float* li = s_l + i * FCH;
            const float* Nj = s_N + j * FCH;
            #pragma unroll 8
            for (int ff = 0; ff < FCH; ff++) {
                float l = li[ff];
                local += logf(expf(l) + Nj[ff]) - l;
            }
        }
        __syncthreads();
    }

    s_red[tid] = local;
    __syncthreads();
    for (int s = 128; s > 0; s >>= 1) {
        if (tid < s) s_red[tid] += s_red[tid + s];
        __syncthreads();
    }
    if (tid == 0) {
        float denom = (float)m * (float)m * (float)NF;
        atomicAdd(out, -(s_red[0] / denom) / (float)BATCH);
    }
}

// ---------------- stream/event side resources (host objects, created pre-main) ----
struct ForkRes {
    cudaStream_t s2;
    cudaEvent_t  evI, evC;
    ForkRes() {
        cudaStreamCreateWithFlags(&s2, cudaStreamNonBlocking);
        cudaEventCreateWithFlags(&evI, cudaEventDisableTiming);
        cudaEventCreateWithFlags(&evC, cudaEventDisableTiming);
    }
};
static ForkRes g_fork;

// ---------------- launch ----------------------------------------------------------
extern "C" void kernel_launch(void* const* d_in, const int* in_sizes, int n_in,
                              void* d_out, int out_size) {
    const float* proba = (const float*)d_in[0];
    const float* y     = (const float*)d_in[1];
    const float* emb   = (const float*)d_in[2];
    float* out = (float*)d_out;
    (void)in_sizes; (void)n_in; (void)out_size;

    kInit<<<256, 256>>>(out);

    // fork after init: the ENTIRE kB chain runs beside kA
    cudaEventRecord(g_fork.evI, 0);
    cudaStreamWaitEvent(g_fork.s2, g_fork.evI, 0);
    kB<<<GB, 256, 0, g_fork.s2>>>(proba);
    kThresh<<<BATCH, 1024, 0, g_fork.s2>>>();
    kCollect<<<1024, 256, 0, g_fork.s2>>>();
    cudaEventRecord(g_fork.evC, g_fork.s2);

    kA<<<GA, 256>>>(y, emb);

    // join: loss needs kA sums + collected candidates
    cudaStreamWaitEvent(0, g_fork.evC, 0);
    kLossSel<<<BATCH * NC, 256>>>(emb, y, out);
}